// round 15
// baseline (speedup 1.0000x reference)
#include <cuda_runtime.h>
#include <cstdint>

// Problem constants
constexpr int kB = 4;
constexpr int kN = 1024;
constexpr int kD = 256;
constexpr int kH = 8;
constexpr int kDH  = kD * kH;          // 2048
constexpr int kNDH = kN * kDH;         // 2097152
constexpr int kSeg = kB * kNDH;        // 8388608  (q/k/v segment, floats)
constexpr int kC3  = 3 * kDH;          // 6144
constexpr int kRows = kB * kN;         // 4096

// Scratch (device globals; no dynamic allocation allowed)
__device__ float g_qkv[3ull * kSeg];   // ~100.7 MB : QKV in reference flat layout
__device__ float g_qkT[2ull * kSeg];   // seg0: Q n-major scaled [bh][n][d]; reused as Av
                                       // seg1: K d-major       [bh][d][n]
__device__ float g_diag[kRows * kH];
__device__ float g_pcs[8 * 32 * kN];      // k2 partial colsums [z][bh][n]
__device__ float g_diagexp[32 * kN];      // exp(S[n,n]) per [bh][n]
__device__ float g_part8[8][kRows * kD];  // k3 K-split partials (32 MB)

// ---------------- cp.async helpers ----------------
__device__ __forceinline__ void cp16(void* smem_dst, const void* gmem_src) {
    unsigned s = (unsigned)__cvta_generic_to_shared(smem_dst);
    asm volatile("cp.async.cg.shared.global [%0], [%1], 16;\n" :: "r"(s), "l"(gmem_src));
}
__device__ __forceinline__ void cp_commit() {
    asm volatile("cp.async.commit_group;\n");
}
template <int N>
__device__ __forceinline__ void cp_wait() {
    asm volatile("cp.async.wait_group %0;\n" :: "n"(N));
}
// Duplicating shared store: [p] <- {v, v}   (no register MOVs needed)
__device__ __forceinline__ void sts2(float* smem_dst, float v) {
    unsigned s = (unsigned)__cvta_generic_to_shared(smem_dst);
    asm volatile("st.shared.v2.f32 [%0], {%1, %1};\n" :: "r"(s), "f"(v));
}

// ---------------- packed f32x2 helpers (Blackwell FFMA2) ----------------
__device__ __forceinline__ void ffma2(uint64_t& d, uint64_t a, uint64_t b) {
    asm("fma.rn.f32x2 %0, %1, %2, %0;" : "+l"(d) : "l"(a), "l"(b));
}
__device__ __forceinline__ float2 unpk2(uint64_t v) {
    uint32_t lo, hi;
    asm("mov.b64 {%0, %1}, %2;" : "=r"(lo), "=r"(hi) : "l"(v));
    return make_float2(__uint_as_float(lo), __uint_as_float(hi));
}

// ---------------------------------------------------------------------------
// Inner loop over one 32-k chunk, A pre-duplicated in smem.
// A_ : [128 rows][68 floats]  (uint64 view: [128][34], elem kg = dup pair of k=kg)
// B_ : k-major [32][132] floats.
// Thread owns rows (wm*64 + r*8 + rowg), cols (wn*32 + colg*8 + 0..7).
// Per 2-k step: 8 A LDS.128 (2 packed pairs each) + 4 B LDS.128 + 64 FFMA2.
// ---------------------------------------------------------------------------
__device__ __forceinline__ void mma_chunk_dup(const float* __restrict__ A_,
                                              const float* __restrict__ B_,
                                              uint64_t (&acc)[8][4],
                                              int wm, int wn, int rowg, int colg)
{
    const uint64_t* A2 = (const uint64_t*)A_;   // row stride 34 uint64
#pragma unroll
    for (int kg = 0; kg < 32; kg += 2) {
        ulonglong2 a2[8];
#pragma unroll
        for (int r = 0; r < 8; r++)
            a2[r] = *(const ulonglong2*)&A2[(wm * 64 + r * 8 + rowg) * 34 + kg];
        {   // k = kg
            const float* brow = &B_[kg * 132 + wn * 32 + colg * 8];
            ulonglong2 q0 = *(const ulonglong2*)brow;
            ulonglong2 q1 = *(const ulonglong2*)(brow + 4);
#pragma unroll
            for (int r = 0; r < 8; r++) {
                ffma2(acc[r][0], a2[r].x, q0.x);
                ffma2(acc[r][1], a2[r].x, q0.y);
                ffma2(acc[r][2], a2[r].x, q1.x);
                ffma2(acc[r][3], a2[r].x, q1.y);
            }
        }
        {   // k = kg + 1
            const float* brow = &B_[(kg + 1) * 132 + wn * 32 + colg * 8];
            ulonglong2 q0 = *(const ulonglong2*)brow;
            ulonglong2 q1 = *(const ulonglong2*)(brow + 4);
#pragma unroll
            for (int r = 0; r < 8; r++) {
                ffma2(acc[r][0], a2[r].y, q0.x);
                ffma2(acc[r][1], a2[r].y, q0.y);
                ffma2(acc[r][2], a2[r].y, q1.x);
                ffma2(acc[r][3], a2[r].y, q1.y);
            }
        }
    }
}

// ---------------------------------------------------------------------------
// Kernel 1: QKV = x @ Wqkv + bqkv     [4096,256] @ [256,6144]
// CTA 128x128; A dup-staged (LDG prefetch + sts2), B cp.async. grid(48,32).
// ---------------------------------------------------------------------------
__global__ __launch_bounds__(256)
void qkv_gemm_kernel(const float* __restrict__ x,
                     const float* __restrict__ W,
                     const float* __restrict__ bias)
{
    extern __shared__ float sm[];
    float* As = sm;                 // [2][128*68]  dup'd
    float* Bs = sm + 2 * 8704;      // [2][32*132]

    const int t = threadIdx.x, lane = t & 31, w = t >> 5;
    const int wm = w & 1, wn = w >> 1;
    const int rowg = lane >> 2, colg = lane & 3;
    const int r0 = blockIdx.y * 128, c0 = blockIdx.x * 128;

    const int ar = t >> 3, ap = t & 7;    // A loader: rows ar+32j, k-part ap
    const int bp = t & 31, br = t >> 5;   // B loader

    uint64_t acc[8][4] = {};
    float4 areg[4];

    auto issueB = [&](int buf, int kc) {
#pragma unroll
        for (int i = 0; i < 4; i++) {
            int k = br + 8 * i;
            cp16(&Bs[buf * 4224 + k * 132 + bp * 4],
                 &W[(size_t)(kc + k) * kC3 + c0 + bp * 4]);
        }
        cp_commit();
    };
    auto loadA = [&](int kc) {
#pragma unroll
        for (int j = 0; j < 4; j++) {
            int m = ar + 32 * j;
            areg[j] = *(const float4*)&x[(size_t)(r0 + m) * kD + kc + ap * 4];
        }
    };
    auto stageA = [&](int buf) {
#pragma unroll
        for (int j = 0; j < 4; j++) {
            int m = ar + 32 * j;
            float* base = &As[buf * 8704 + m * 68 + ap * 8];
            sts2(base + 0, areg[j].x);
            sts2(base + 2, areg[j].y);
            sts2(base + 4, areg[j].z);
            sts2(base + 6, areg[j].w);
        }
    };

    issueB(0, 0);
    loadA(0);
    for (int c = 0; c < 8; c++) {
        const int buf = c & 1;
        cp_wait<0>();
        stageA(buf);
        if (c < 7) { issueB(buf ^ 1, (c + 1) * 32); loadA((c + 1) * 32); }
        __syncthreads();
        mma_chunk_dup(&As[buf * 8704], &Bs[buf * 4224], acc, wm, wn, rowg, colg);
        __syncthreads();
    }

    const int cbase = c0 + wn * 32 + colg * 8;
#pragma unroll
    for (int r = 0; r < 8; r++) {
        int row = r0 + wm * 64 + r * 8 + rowg;
        float2 u0 = unpk2(acc[r][0]), u1 = unpk2(acc[r][1]);
        float2 u2 = unpk2(acc[r][2]), u3 = unpk2(acc[r][3]);
        float4 v0, v1;
        v0.x = u0.x + bias[cbase + 0]; v0.y = u0.y + bias[cbase + 1];
        v0.z = u1.x + bias[cbase + 2]; v0.w = u1.y + bias[cbase + 3];
        v1.x = u2.x + bias[cbase + 4]; v1.y = u2.y + bias[cbase + 5];
        v1.z = u3.x + bias[cbase + 6]; v1.w = u3.y + bias[cbase + 7];
        *(float4*)&g_qkv[(size_t)row * kC3 + cbase] = v0;
        *(float4*)&g_qkv[(size_t)row * kC3 + cbase + 4] = v1;
    }
}

// ---------------------------------------------------------------------------
// Transpose: q -> [bh][n][d] (scaled 1/16);  k -> [bh][d][n]. (proven, verbatim)
// ---------------------------------------------------------------------------
__global__ __launch_bounds__(256)
void transpose_qk_kernel()
{
    __shared__ float smt[8][32][33];   // [h][qd][n]
    const int bid = blockIdx.x;
    const int qb  = bid & 7;
    const int nb  = (bid >> 3) & 31;
    const int b   = (bid >> 8) & 3;
    const int seg = bid >> 10;
    const int t   = threadIdx.x;

    const float* src = g_qkv + (size_t)seg * kSeg + (size_t)b * kNDH
                     + (size_t)(nb * 32) * kDH + qb * 32 * 8;
    {
        const int nl = t >> 3, f = t & 7;
        const int h0 = (f & 1) * 4, q0 = f >> 1;
#pragma unroll
        for (int i = 0; i < 8; i++) {
            float4 v = *(const float4*)&src[(size_t)nl * kDH + (f + i * 8) * 4];
            int ql = q0 + i * 4;
            smt[h0 + 0][ql][nl] = v.x;
            smt[h0 + 1][ql][nl] = v.y;
            smt[h0 + 2][ql][nl] = v.z;
            smt[h0 + 3][ql][nl] = v.w;
        }
    }
    __syncthreads();
    if (seg == 0) {
        const int q4 = (t & 7) * 4, hn = t >> 3;
#pragma unroll
        for (int i = 0; i < 8; i++) {
            int idx = hn + i * 32;
            int h = idx >> 5, n = idx & 31;
            float4 v;
            v.x = smt[h][q4 + 0][n] * 0.0625f;
            v.y = smt[h][q4 + 1][n] * 0.0625f;
            v.z = smt[h][q4 + 2][n] * 0.0625f;
            v.w = smt[h][q4 + 3][n] * 0.0625f;
            float* dst = g_qkT
                       + (((size_t)(b * 8 + h) * kN + nb * 32 + n) * kD)
                       + qb * 32 + q4;
            *(float4*)dst = v;
        }
    } else {
#pragma unroll
        for (int i = 0; i < 8; i++) {
            int idx = t + i * 256;
            int h = idx >> 8, rem = idx & 255;
            int q = rem >> 3, nf = rem & 7;
            float4 v;
            v.x = smt[h][q][nf * 4 + 0];
            v.y = smt[h][q][nf * 4 + 1];
            v.z = smt[h][q][nf * 4 + 2];
            v.w = smt[h][q][nf * 4 + 3];
            float* dst = g_qkT + (size_t)kSeg
                       + (((size_t)(b * 8 + h) * kD + qb * 32 + q) * kN)
                       + nb * 32 + nf * 4;
            *(float4*)dst = v;
        }
    }
}

// ---------------------------------------------------------------------------
// Kernel 2: per (b,h,z): colsums of exp(S) for ONE 128-m tile (m0 = z*128),
// plus diag-exp when z == n-tile. A (Q) dup-staged, B (K d-major) cp.async.
// grid(8, 32, 8) = 2048 CTAs.
// ---------------------------------------------------------------------------
__global__ __launch_bounds__(256)
void score_diag_kernel()
{
    extern __shared__ float sm[];
    float* As     = sm;                        // [2][128*68] dup'd
    float* Ks     = sm + 2 * 8704;             // [2][32*132]
    float* red    = sm + 2 * 8704 + 2 * 4224;  // [16*128]
    float* diagsm = red + 2048;                // [128]

    const int t = threadIdx.x, lane = t & 31, w = t >> 5;
    const int wm = w & 1, wn = w >> 1;
    const int rowg = lane >> 2, colg = lane & 3;
    const int bh = blockIdx.y;
    const int n0 = blockIdx.x * 128;
    const int z  = blockIdx.z;
    const int m0 = z * 128;

    const float* Q  = g_qkT + (size_t)bh * (kN * kD);                 // [n][d]
    const float* Kd = g_qkT + (size_t)kSeg + (size_t)bh * (kD * kN);  // [d][n]

    const int ar = t >> 3, ap = t & 7;
    const int bp = t & 31, br = t >> 5;

    const bool diagtile = (z == (int)blockIdx.x);

    uint64_t acc[8][4] = {};
    float4 areg[4];

    auto issueB = [&](int buf, int kc) {
#pragma unroll
        for (int i = 0; i < 4; i++) {
            int k = br + 8 * i;
            cp16(&Ks[buf * 4224 + k * 132 + bp * 4],
                 &Kd[(size_t)(kc + k) * kN + n0 + bp * 4]);
        }
        cp_commit();
    };
    auto loadA = [&](int kc) {
#pragma unroll
        for (int j = 0; j < 4; j++) {
            int m = ar + 32 * j;
            areg[j] = *(const float4*)&Q[(size_t)(m0 + m) * kD + kc + ap * 4];
        }
    };
    auto stageA = [&](int buf) {
#pragma unroll
        for (int j = 0; j < 4; j++) {
            int m = ar + 32 * j;
            float* base = &As[buf * 8704 + m * 68 + ap * 8];
            sts2(base + 0, areg[j].x);
            sts2(base + 2, areg[j].y);
            sts2(base + 4, areg[j].z);
            sts2(base + 6, areg[j].w);
        }
    };

    issueB(0, 0);
    loadA(0);
    for (int c = 0; c < 8; c++) {
        const int buf = c & 1;
        cp_wait<0>();
        stageA(buf);
        if (c < 7) { issueB(buf ^ 1, (c + 1) * 32); loadA((c + 1) * 32); }
        __syncthreads();
        mma_chunk_dup(&As[buf * 8704], &Ks[buf * 4224], acc, wm, wn, rowg, colg);
        __syncthreads();
    }

    // ---- epilogue: exp + colsum; diagonal -> smem ----
    float colsum[8];
    const int clb = wn * 32 + colg * 8;
#pragma unroll
    for (int jp = 0; jp < 4; jp++) {
        float s0 = 0.f, s1 = 0.f;
#pragma unroll
        for (int r = 0; r < 8; r++) {
            float2 u = unpk2(acc[r][jp]);
            float e0 = __expf(u.x), e1 = __expf(u.y);
            s0 += e0; s1 += e1;
            if (diagtile) {
                int lm = wm * 64 + r * 8 + rowg;
                if (lm == clb + 2 * jp)     diagsm[clb + 2 * jp]     = e0;
                if (lm == clb + 2 * jp + 1) diagsm[clb + 2 * jp + 1] = e1;
            }
        }
        colsum[2 * jp]     = s0;
        colsum[2 * jp + 1] = s1;
    }

    const int slot = wm * 8 + rowg;
#pragma unroll
    for (int j = 0; j < 8; j++)
        red[slot * 128 + clb + j] = colsum[j];
    __syncthreads();
    if (t < 128) {
        float total = red[t];
#pragma unroll
        for (int r = 1; r < 16; r++) total += red[r * 128 + t];
        g_pcs[((size_t)z * 32 + bh) * kN + n0 + t] = total;
        if (diagtile)
            g_diagexp[(size_t)bh * kN + n0 + t] = diagsm[t];
    }
}

// ---------------------------------------------------------------------------
// Kernel 2b: g_diag = diagexp / sum_z pcs
// ---------------------------------------------------------------------------
__global__ __launch_bounds__(256)
void finish_diag()
{
    int id = blockIdx.x * 256 + threadIdx.x;   // 32768 = 32 bh x 1024 n
    int bh = id >> 10, n = id & 1023;
    float tot = 0.f;
#pragma unroll
    for (int z = 0; z < 8; z++)
        tot += g_pcs[((size_t)z * 32 + bh) * kN + n];
    int b = bh >> 3, h = bh & 7;
    g_diag[((size_t)b * kN + n) * kH + h] = g_diagexp[(size_t)bh * kN + n] / tot;
}

// ---------------------------------------------------------------------------
// Kernel 2c: Av = diag .* v  -> g_qkT seg0 (Q is dead after k2)
// ---------------------------------------------------------------------------
__global__ __launch_bounds__(256)
void av_kernel()
{
    const float* vseg = g_qkv + 2ull * kSeg;
    int idx = (blockIdx.x * 256 + threadIdx.x) * 4;   // 8388608 elems total
    int r = idx >> 11;
    int c = idx & 2047;
    float4 v = *(const float4*)&vseg[idx];
    float4 dv = *(const float4*)&g_diag[r * 8 + (c & 4)];
    v.x *= dv.x; v.y *= dv.y; v.z *= dv.z; v.w *= dv.w;
    *(float4*)&g_qkT[idx] = v;
}

// ---------------------------------------------------------------------------
// Kernel 3: partial = Av @ W0, K-split 8.  [4096,2048]@[2048,256]
// CTA 128m x 128n over 256-wide K slice. A dup-staged, B cp.async.
// grid(2, 32, 8) = 512 CTAs (3.5 waves at 1 CTA/SM).
// ---------------------------------------------------------------------------
__global__ __launch_bounds__(256)
void out_gemm_kernel(const float* __restrict__ W0)
{
    extern __shared__ float sm[];
    float* As = sm;                 // [2][128*68] dup'd
    float* Ws = sm + 2 * 8704;      // [2][32*132]

    const int t = threadIdx.x, lane = t & 31, w = t >> 5;
    const int wm = w & 1, wn = w >> 1;
    const int rowg = lane >> 2, colg = lane & 3;
    const int c0 = blockIdx.x * 128;
    const int r0 = blockIdx.y * 128;
    const int kb = blockIdx.z * 256;
    float* dst = g_part8[blockIdx.z];

    const int ar = t >> 3, ap = t & 7;
    const int bp = t & 31, br = t >> 5;

    uint64_t acc[8][4] = {};
    float4 areg[4];

    auto issueB = [&](int buf, int kc) {
#pragma unroll
        for (int i = 0; i < 4; i++) {
            int k = br + 8 * i;
            cp16(&Ws[buf * 4224 + k * 132 + bp * 4],
                 &W0[(size_t)(kb + kc + k) * kD + c0 + bp * 4]);
        }
        cp_commit();
    };
    auto loadA = [&](int kc) {
#pragma unroll
        for (int j = 0; j < 4; j++) {
            int m = ar + 32 * j;
            areg[j] = *(const float4*)
                &g_qkT[(size_t)(r0 + m) * kDH + kb + kc + ap * 4];
        }
    };
    auto stageA = [&](int buf) {
#pragma unroll
        for (int j = 0; j < 4; j++) {
            int m = ar + 32 * j;
            float* base = &As[buf * 8704 + m * 68 + ap * 8];
            sts2(base + 0, areg[j].x);
            sts2(base + 2, areg[j].y);
            sts2(base + 4, areg[j].z);
            sts2(base + 6, areg[j].w);
        }
    };

    issueB(0, 0);
    loadA(0);
    for (int c = 0; c < 8; c++) {
        const int buf = c & 1;
        cp_wait<0>();
        stageA(buf);
        if (c < 7) { issueB(buf ^ 1, (c + 1) * 32); loadA((c + 1) * 32); }
        __syncthreads();
        mma_chunk_dup(&As[buf * 8704], &Ws[buf * 4224], acc, wm, wn, rowg, colg);
        __syncthreads();
    }

    const int cbase = c0 + wn * 32 + colg * 8;
#pragma unroll
    for (int r = 0; r < 8; r++) {
        int row = r0 + wm * 64 + r * 8 + rowg;
        float2 u0 = unpk2(acc[r][0]), u1 = unpk2(acc[r][1]);
        float2 u2 = unpk2(acc[r][2]), u3 = unpk2(acc[r][3]);
        float4 v0 = {u0.x, u0.y, u1.x, u1.y};
        float4 v1 = {u2.x, u2.y, u3.x, u3.y};
        *(float4*)&dst[(size_t)row * kD + cbase] = v0;
        *(float4*)&dst[(size_t)row * kD + cbase + 4] = v1;
    }
}

// ---------------------------------------------------------------------------
// Kernel 3b: out = sum of 8 partials + b0
// ---------------------------------------------------------------------------
__global__ __launch_bounds__(256)
void out_combine(const float* __restrict__ b0, float* __restrict__ out)
{
    int i4 = blockIdx.x * 256 + threadIdx.x;     // float4 index, 262144 total
    size_t off = (size_t)i4 * 4;
    float4 s = *(const float4*)&g_part8[0][off];
#pragma unroll
    for (int z = 1; z < 8; z++) {
        float4 p = *(const float4*)&g_part8[z][off];
        s.x += p.x; s.y += p.y; s.z += p.z; s.w += p.w;
    }
    float4 bb = *(const float4*)&b0[(i4 & 63) * 4];
    s.x += bb.x; s.y += bb.y; s.z += bb.z; s.w += bb.w;
    *(float4*)&out[off] = s;
}

// ---------------------------------------------------------------------------
extern "C" void kernel_launch(void* const* d_in, const int* in_sizes, int n_in,
                              void* d_out, int out_size)
{
    const float *x = nullptr, *Wqkv = nullptr, *bqkv = nullptr,
                *W0 = nullptr, *b0 = nullptr;
    for (int i = 0; i < n_in; i++) {
        switch (in_sizes[i]) {
            case kRows * kD: x    = (const float*)d_in[i]; break;
            case kD * kC3:   Wqkv = (const float*)d_in[i]; break;
            case kC3:        bqkv = (const float*)d_in[i]; break;
            case kDH * kD:   W0   = (const float*)d_in[i]; break;
            case kD:         b0   = (const float*)d_in[i]; break;
            default: break;
        }
    }
    float* out = (float*)d_out;

    const size_t smem1 = (size_t)(2 * 8704 + 2 * 4224) * sizeof(float);              // 103424
    const size_t smem2 = (size_t)(2 * 8704 + 2 * 4224 + 2048 + 128) * sizeof(float); // 112128
    const size_t smem3 = smem1;
    static bool attr_done = false;
    if (!attr_done) {
        cudaFuncSetAttribute(qkv_gemm_kernel,
                             cudaFuncAttributeMaxDynamicSharedMemorySize, (int)smem1);
        cudaFuncSetAttribute(score_diag_kernel,
                             cudaFuncAttributeMaxDynamicSharedMemorySize, (int)smem2);
        cudaFuncSetAttribute(out_gemm_kernel,
                             cudaFuncAttributeMaxDynamicSharedMemorySize, (int)smem3);
        attr_done = true;
    }

    qkv_gemm_kernel<<<dim3(kC3 / 128, kRows / 128), 256, smem1>>>(x, Wqkv, bqkv);
    transpose_qk_kernel<<<2048, 256>>>();
    score_diag_kernel<<<dim3(kN / 128, kB * kH, 8), 256, smem2>>>();
    finish_diag<<<128, 256>>>();
    av_kernel<<<8192, 256>>>();
    out_gemm_kernel<<<dim3(kD / 128, kRows / 128, 8), 256, smem3>>>(W0);
    out_combine<<<1024, 256>>>(b0, out);
}

// round 16
// speedup vs baseline: 1.1634x; 1.1634x over previous
#include <cuda_runtime.h>
#include <cstdint>

// Problem constants
constexpr int kB = 4;
constexpr int kN = 1024;
constexpr int kD = 256;
constexpr int kH = 8;
constexpr int kDH  = kD * kH;          // 2048
constexpr int kNDH = kN * kDH;         // 2097152
constexpr int kSeg = kB * kNDH;        // 8388608  (q/k/v segment, floats)
constexpr int kC3  = 3 * kDH;          // 6144
constexpr int kRows = kB * kN;         // 4096

// Scratch (device globals; no dynamic allocation allowed)
__device__ float g_qkv[3ull * kSeg];   // ~100.7 MB : QKV in reference flat layout
__device__ float g_qkT[2ull * kSeg];   // seg0: Q n-major scaled [bh][n][d]; reused as Av
                                       // seg1: K d-major       [bh][d][n]
__device__ float g_diag[kRows * kH];
__device__ float g_pcs[16 * 32 * kN];     // k2 partial colsums [z][bh][n]
__device__ float g_diagexp[32 * kN];      // exp(S[n,n]) per [bh][n]
__device__ float g_part8[8][kRows * kD];  // k3 K-split partials (32 MB)

// ---------------- cp.async helpers ----------------
__device__ __forceinline__ void cp16(void* smem_dst, const void* gmem_src) {
    unsigned s = (unsigned)__cvta_generic_to_shared(smem_dst);
    asm volatile("cp.async.cg.shared.global [%0], [%1], 16;\n" :: "r"(s), "l"(gmem_src));
}
__device__ __forceinline__ void cp_commit() {
    asm volatile("cp.async.commit_group;\n");
}
template <int N>
__device__ __forceinline__ void cp_wait() {
    asm volatile("cp.async.wait_group %0;\n" :: "n"(N));
}

// ---------------- packed f32x2 helpers (Blackwell FFMA2) ----------------
__device__ __forceinline__ void ffma2(uint64_t& d, uint64_t a, uint64_t b) {
    asm("fma.rn.f32x2 %0, %1, %2, %0;" : "+l"(d) : "l"(a), "l"(b));
}
__device__ __forceinline__ uint64_t bcast2(float x) {
    uint64_t r;
    asm("mov.b64 %0, {%1, %1};" : "=l"(r) : "r"(__float_as_uint(x)));
    return r;
}
__device__ __forceinline__ float2 unpk2(uint64_t v) {
    uint32_t lo, hi;
    asm("mov.b64 {%0, %1}, %2;" : "=r"(lo), "=r"(hi) : "l"(v));
    return make_float2(__uint_as_float(lo), __uint_as_float(hi));
}
__device__ __forceinline__ float selc(float4 v, int kk) {
    return (kk == 0) ? v.x : (kk == 1) ? v.y : (kk == 2) ? v.z : v.w;
}

// Shared inner-loop: one 32-k chunk of a 128x128 tile.
// A_ m-major [128][36]; B_ k-major [32][132].
__device__ __forceinline__ void mma_chunk(const float* __restrict__ A_,
                                          const float* __restrict__ B_,
                                          uint64_t (&acc)[8][4],
                                          int wm, int wn, int rowg, int colg)
{
#pragma unroll
    for (int kg = 0; kg < 32; kg += 4) {
        float4 av[8];
#pragma unroll
        for (int r = 0; r < 8; r++)
            av[r] = *(const float4*)&A_[(wm * 64 + r * 8 + rowg) * 36 + kg];
#pragma unroll
        for (int kk = 0; kk < 4; kk++) {
            const float* brow = &B_[(kg + kk) * 132 + wn * 32 + colg * 8];
            ulonglong2 q0 = *(const ulonglong2*)brow;
            ulonglong2 q1 = *(const ulonglong2*)(brow + 4);
#pragma unroll
            for (int r = 0; r < 8; r++) {
                uint64_t a2 = bcast2(selc(av[r], kk));
                ffma2(acc[r][0], a2, q0.x);
                ffma2(acc[r][1], a2, q0.y);
                ffma2(acc[r][2], a2, q1.x);
                ffma2(acc[r][3], a2, q1.y);
            }
        }
    }
}

// 64-row variant (CTA 64m x 128n, thread 4x8).
__device__ __forceinline__ void mma_chunk64(const float* __restrict__ A_,
                                            const float* __restrict__ B_,
                                            uint64_t (&acc)[4][4],
                                            int wm, int wn, int rowg, int colg)
{
#pragma unroll
    for (int kg = 0; kg < 32; kg += 4) {
        float4 av[4];
#pragma unroll
        for (int r = 0; r < 4; r++)
            av[r] = *(const float4*)&A_[(wm * 32 + r * 8 + rowg) * 36 + kg];
#pragma unroll
        for (int kk = 0; kk < 4; kk++) {
            const float* brow = &B_[(kg + kk) * 132 + wn * 32 + colg * 8];
            ulonglong2 q0 = *(const ulonglong2*)brow;
            ulonglong2 q1 = *(const ulonglong2*)(brow + 4);
#pragma unroll
            for (int r = 0; r < 4; r++) {
                uint64_t a2 = bcast2(selc(av[r], kk));
                ffma2(acc[r][0], a2, q0.x);
                ffma2(acc[r][1], a2, q0.y);
                ffma2(acc[r][2], a2, q1.x);
                ffma2(acc[r][3], a2, q1.y);
            }
        }
    }
}

// ---------------------------------------------------------------------------
// Kernel 1: QKV = x @ Wqkv + bqkv     [4096,256] @ [256,6144]
// CTA 128x128, warp 64x32, thread 8x8 packed, single-sync pipeline.
// grid(48, 32) = 1536 CTAs. (round-14 proven, verbatim)
// ---------------------------------------------------------------------------
__global__ __launch_bounds__(256, 2)
void qkv_gemm_kernel(const float* __restrict__ x,
                     const float* __restrict__ W,
                     const float* __restrict__ bias)
{
    extern __shared__ float sm[];
    float* As = sm;                 // [2][128*36]
    float* Bs = sm + 2 * 4608;      // [2][32*132]

    const int t = threadIdx.x, lane = t & 31, w = t >> 5;
    const int wm = w & 1, wn = w >> 1;
    const int rowg = lane >> 2, colg = lane & 3;
    const int r0 = blockIdx.y * 128, c0 = blockIdx.x * 128;

    const int ar = t >> 3, ap = t & 7;
    const int bp = t & 31, br = t >> 5;

    uint64_t acc[8][4] = {};

    auto issue = [&](int buf, int kc) {
#pragma unroll
        for (int j = 0; j < 4; j++) {
            int m = ar + 32 * j;
            cp16(&As[buf * 4608 + m * 36 + ap * 4],
                 &x[(size_t)(r0 + m) * kD + kc + ap * 4]);
        }
#pragma unroll
        for (int i = 0; i < 4; i++) {
            int k = br + 8 * i;
            cp16(&Bs[buf * 4224 + k * 132 + bp * 4],
                 &W[(size_t)(kc + k) * kC3 + c0 + bp * 4]);
        }
        cp_commit();
    };

    issue(0, 0);
    for (int c = 0; c < 8; c++) {
        const int buf = c & 1;
        cp_wait<0>();
        __syncthreads();
        if (c < 7) issue(buf ^ 1, (c + 1) * 32);
        mma_chunk(&As[buf * 4608], &Bs[buf * 4224], acc, wm, wn, rowg, colg);
    }

    const int cbase = c0 + wn * 32 + colg * 8;
#pragma unroll
    for (int r = 0; r < 8; r++) {
        int row = r0 + wm * 64 + r * 8 + rowg;
        float2 u0 = unpk2(acc[r][0]), u1 = unpk2(acc[r][1]);
        float2 u2 = unpk2(acc[r][2]), u3 = unpk2(acc[r][3]);
        float4 v0, v1;
        v0.x = u0.x + bias[cbase + 0]; v0.y = u0.y + bias[cbase + 1];
        v0.z = u1.x + bias[cbase + 2]; v0.w = u1.y + bias[cbase + 3];
        v1.x = u2.x + bias[cbase + 4]; v1.y = u2.y + bias[cbase + 5];
        v1.z = u3.x + bias[cbase + 6]; v1.w = u3.y + bias[cbase + 7];
        *(float4*)&g_qkv[(size_t)row * kC3 + cbase] = v0;
        *(float4*)&g_qkv[(size_t)row * kC3 + cbase + 4] = v1;
    }
}

// ---------------------------------------------------------------------------
// Transpose: q -> [bh][n][d] (scaled 1/16);  k -> [bh][d][n]. (proven, verbatim)
// ---------------------------------------------------------------------------
__global__ __launch_bounds__(256)
void transpose_qk_kernel()
{
    __shared__ float smt[8][32][33];   // [h][qd][n]
    const int bid = blockIdx.x;
    const int qb  = bid & 7;
    const int nb  = (bid >> 3) & 31;
    const int b   = (bid >> 8) & 3;
    const int seg = bid >> 10;
    const int t   = threadIdx.x;

    const float* src = g_qkv + (size_t)seg * kSeg + (size_t)b * kNDH
                     + (size_t)(nb * 32) * kDH + qb * 32 * 8;
    {
        const int nl = t >> 3, f = t & 7;
        const int h0 = (f & 1) * 4, q0 = f >> 1;
#pragma unroll
        for (int i = 0; i < 8; i++) {
            float4 v = *(const float4*)&src[(size_t)nl * kDH + (f + i * 8) * 4];
            int ql = q0 + i * 4;
            smt[h0 + 0][ql][nl] = v.x;
            smt[h0 + 1][ql][nl] = v.y;
            smt[h0 + 2][ql][nl] = v.z;
            smt[h0 + 3][ql][nl] = v.w;
        }
    }
    __syncthreads();
    if (seg == 0) {
        const int q4 = (t & 7) * 4, hn = t >> 3;
#pragma unroll
        for (int i = 0; i < 8; i++) {
            int idx = hn + i * 32;
            int h = idx >> 5, n = idx & 31;
            float4 v;
            v.x = smt[h][q4 + 0][n] * 0.0625f;
            v.y = smt[h][q4 + 1][n] * 0.0625f;
            v.z = smt[h][q4 + 2][n] * 0.0625f;
            v.w = smt[h][q4 + 3][n] * 0.0625f;
            float* dst = g_qkT
                       + (((size_t)(b * 8 + h) * kN + nb * 32 + n) * kD)
                       + qb * 32 + q4;
            *(float4*)dst = v;
        }
    } else {
#pragma unroll
        for (int i = 0; i < 8; i++) {
            int idx = t + i * 256;
            int h = idx >> 8, rem = idx & 255;
            int q = rem >> 3, nf = rem & 7;
            float4 v;
            v.x = smt[h][q][nf * 4 + 0];
            v.y = smt[h][q][nf * 4 + 1];
            v.z = smt[h][q][nf * 4 + 2];
            v.w = smt[h][q][nf * 4 + 3];
            float* dst = g_qkT + (size_t)kSeg
                       + (((size_t)(b * 8 + h) * kD + qb * 32 + q) * kN)
                       + nb * 32 + nf * 4;
            *(float4*)dst = v;
        }
    }
}

// ---------------------------------------------------------------------------
// Kernel 2: per (b,h,z): colsums of exp(S) for ONE 64-m tile (m0 = z*64).
// CTA 64m x 128n, thread 4x8 packed, 3 CTAs/SM. grid(8, 32, 16) = 4096 CTAs.
// Diagonal: CTA (x=bx, z) overlaps diag iff (z>>1)==bx; even z owns local
// cols 0..63, odd z owns 64..127 (lc = lm + (z&1)*64).
// ---------------------------------------------------------------------------
__global__ __launch_bounds__(256, 3)
void score_diag_kernel()
{
    extern __shared__ float sm[];
    float* As     = sm;                        // [2][64*36]  = 2*2304
    float* Ks     = sm + 2 * 2304;             // [2][32*132] = 2*4224
    float* red    = sm + 2 * 2304 + 2 * 4224;  // [8*128]
    float* diagsm = red + 1024;                // [128]

    const int t = threadIdx.x, lane = t & 31, w = t >> 5;
    const int wm = w & 1, wn = w >> 1;
    const int rowg = lane >> 2, colg = lane & 3;
    const int bh = blockIdx.y;
    const int n0 = blockIdx.x * 128;
    const int z  = blockIdx.z;                 // m-tile 0..15
    const int m0 = z * 64;

    const float* Q  = g_qkT + (size_t)bh * (kN * kD);                 // [n][d]
    const float* Kd = g_qkT + (size_t)kSeg + (size_t)bh * (kD * kN);  // [d][n]

    const int ar = t >> 3, ap = t & 7;    // A loader: rows ar+32j (j<2)
    const int bp = t & 31, br = t >> 5;

    const bool diagtile = ((z >> 1) == (int)blockIdx.x);
    const int  doff = (z & 1) * 64;            // local col offset of diagonal

    uint64_t acc[4][4] = {};

    auto issue = [&](int buf, int kc) {
#pragma unroll
        for (int j = 0; j < 2; j++) {
            int m = ar + 32 * j;
            cp16(&As[buf * 2304 + m * 36 + ap * 4],
                 &Q[(size_t)(m0 + m) * kD + kc + ap * 4]);
        }
#pragma unroll
        for (int i = 0; i < 4; i++) {
            int k = br + 8 * i;
            cp16(&Ks[buf * 4224 + k * 132 + bp * 4],
                 &Kd[(size_t)(kc + k) * kN + n0 + bp * 4]);
        }
        cp_commit();
    };

    issue(0, 0);
    for (int c = 0; c < 8; c++) {
        const int buf = c & 1;
        cp_wait<0>();
        __syncthreads();
        if (c < 7) issue(buf ^ 1, (c + 1) * 32);
        mma_chunk64(&As[buf * 2304], &Ks[buf * 4224], acc, wm, wn, rowg, colg);
    }

    // ---- epilogue: exp + colsum; diagonal -> smem ----
    float colsum[8];
    const int clb = wn * 32 + colg * 8;
#pragma unroll
    for (int jp = 0; jp < 4; jp++) {
        float s0 = 0.f, s1 = 0.f;
#pragma unroll
        for (int r = 0; r < 4; r++) {
            float2 u = unpk2(acc[r][jp]);
            float e0 = __expf(u.x), e1 = __expf(u.y);
            s0 += e0; s1 += e1;
            if (diagtile) {
                int lc = wm * 32 + r * 8 + rowg + doff;   // diag local col
                if (lc == clb + 2 * jp)     diagsm[lc]     = e0;
                if (lc == clb + 2 * jp + 1) diagsm[lc]     = e1;
            }
        }
        colsum[2 * jp]     = s0;
        colsum[2 * jp + 1] = s1;
    }

    // ---- reduction across the 8 (wm,rowg) slots; write partials ----
    const int slot = wm * 8 + rowg;   // 0..15, but rows fold: use 8 slots of 128
    // two wm values share rows? no: wm in {0,1}, rowg 0..7 -> 16 slots; fold to 8
    // by pre-summing pairs in smem: write to slot & 7 with atomic-free two-pass.
    // Simpler: 16 slots of 64-wide? Keep 8x128: sum wm halves via offset add.
#pragma unroll
    for (int j = 0; j < 8; j++) {
        // first wm=0 writes, then wm=1 adds after a barrier
        if (wm == 0) red[slot * 128 + clb + j] = colsum[j];
    }
    __syncthreads();
#pragma unroll
    for (int j = 0; j < 8; j++) {
        if (wm == 1) red[(slot - 8) * 128 + clb + j] += colsum[j];
    }
    __syncthreads();
    if (t < 128) {
        float total = red[t];
#pragma unroll
        for (int r = 1; r < 8; r++) total += red[r * 128 + t];
        g_pcs[((size_t)z * 32 + bh) * kN + n0 + t] = total;
        if (diagtile && (t >> 6) == (z & 1))
            g_diagexp[(size_t)bh * kN + n0 + t] = diagsm[t];
    }
}

// ---------------------------------------------------------------------------
// Kernel 2b: g_diag = diagexp / sum_z pcs  (16 slices)
// ---------------------------------------------------------------------------
__global__ __launch_bounds__(256)
void finish_diag()
{
    int id = blockIdx.x * 256 + threadIdx.x;   // 32768 = 32 bh x 1024 n
    int bh = id >> 10, n = id & 1023;
    float tot = 0.f;
#pragma unroll
    for (int z = 0; z < 16; z++)
        tot += g_pcs[((size_t)z * 32 + bh) * kN + n];
    int b = bh >> 3, h = bh & 7;
    g_diag[((size_t)b * kN + n) * kH + h] = g_diagexp[(size_t)bh * kN + n] / tot;
}

// ---------------------------------------------------------------------------
// Kernel 2c: Av = diag .* v  -> g_qkT seg0 (Q dead after k2). (proven)
// ---------------------------------------------------------------------------
__global__ __launch_bounds__(256)
void av_kernel()
{
    const float* vseg = g_qkv + 2ull * kSeg;
    int idx = (blockIdx.x * 256 + threadIdx.x) * 4;
    int r = idx >> 11;
    int c = idx & 2047;
    float4 v = *(const float4*)&vseg[idx];
    float4 dv = *(const float4*)&g_diag[r * 8 + (c & 4)];
    v.x *= dv.x; v.y *= dv.y; v.z *= dv.z; v.w *= dv.w;
    *(float4*)&g_qkT[idx] = v;
}

// ---------------------------------------------------------------------------
// Kernel 3: partial = Av @ W0, K-split 8.  [4096,2048]@[2048,256]
// CTA 64m x 128n, thread 4x8 packed. grid(2, 64, 8) = 1024 CTAs.
// (round-14 proven, verbatim)
// ---------------------------------------------------------------------------
__global__ __launch_bounds__(256, 2)
void out_gemm_kernel(const float* __restrict__ W0)
{
    extern __shared__ float sm[];
    float* As = sm;                 // [2][64*36]
    float* Ws = sm + 2 * 2304;      // [2][32*132]

    const int t = threadIdx.x, lane = t & 31, w = t >> 5;
    const int wm = w & 1, wn = w >> 1;
    const int rowg = lane >> 2, colg = lane & 3;
    const int c0 = blockIdx.x * 128;
    const int r0 = blockIdx.y * 64;
    const int kb = blockIdx.z * 256;
    float* dst = g_part8[blockIdx.z];

    const int ar = t >> 3, ap = t & 7;
    const int bp = t & 31, br = t >> 5;

    uint64_t acc[4][4] = {};

    auto issue = [&](int buf, int kc) {
#pragma unroll
        for (int j = 0; j < 2; j++) {
            int m = ar + 32 * j;
            cp16(&As[buf * 2304 + m * 36 + ap * 4],
                 &g_qkT[(size_t)(r0 + m) * kDH + kb + kc + ap * 4]);
        }
#pragma unroll
        for (int i = 0; i < 4; i++) {
            int k = br + 8 * i;
            cp16(&Ws[buf * 4224 + k * 132 + bp * 4],
                 &W0[(size_t)(kb + kc + k) * kD + c0 + bp * 4]);
        }
        cp_commit();
    };

    issue(0, 0);
    for (int c = 0; c < 8; c++) {
        const int buf = c & 1;
        cp_wait<0>();
        __syncthreads();
        if (c < 7) issue(buf ^ 1, (c + 1) * 32);
        mma_chunk64(&As[buf * 2304], &Ws[buf * 4224], acc, wm, wn, rowg, colg);
    }

    const int cbase = c0 + wn * 32 + colg * 8;
#pragma unroll
    for (int r = 0; r < 4; r++) {
        int row = r0 + wm * 32 + r * 8 + rowg;
        float2 u0 = unpk2(acc[r][0]), u1 = unpk2(acc[r][1]);
        float2 u2 = unpk2(acc[r][2]), u3 = unpk2(acc[r][3]);
        float4 v0 = {u0.x, u0.y, u1.x, u1.y};
        float4 v1 = {u2.x, u2.y, u3.x, u3.y};
        *(float4*)&dst[(size_t)row * kD + cbase] = v0;
        *(float4*)&dst[(size_t)row * kD + cbase + 4] = v1;
    }
}

// ---------------------------------------------------------------------------
// Kernel 3b: out = sum of 8 partials + b0
// ---------------------------------------------------------------------------
__global__ __launch_bounds__(256)
void out_combine(const float* __restrict__ b0, float* __restrict__ out)
{
    int i4 = blockIdx.x * 256 + threadIdx.x;     // float4 index, 262144 total
    size_t off = (size_t)i4 * 4;
    float4 s = *(const float4*)&g_part8[0][off];
#pragma unroll
    for (int z = 1; z < 8; z++) {
        float4 p = *(const float4*)&g_part8[z][off];
        s.x += p.x; s.y += p.y; s.z += p.z; s.w += p.w;
    }
    float4 bb = *(const float4*)&b0[(i4 & 63) * 4];
    s.x += bb.x; s.y += bb.y; s.z += bb.z; s.w += bb.w;
    *(float4*)&out[off] = s;
}

// ---------------------------------------------------------------------------
extern "C" void kernel_launch(void* const* d_in, const int* in_sizes, int n_in,
                              void* d_out, int out_size)
{
    const float *x = nullptr, *Wqkv = nullptr, *bqkv = nullptr,
                *W0 = nullptr, *b0 = nullptr;
    for (int i = 0; i < n_in; i++) {
        switch (in_sizes[i]) {
            case kRows * kD: x    = (const float*)d_in[i]; break;
            case kD * kC3:   Wqkv = (const float*)d_in[i]; break;
            case kC3:        bqkv = (const float*)d_in[i]; break;
            case kDH * kD:   W0   = (const float*)d_in[i]; break;
            case kD:         b0   = (const float*)d_in[i]; break;
            default: break;
        }
    }
    float* out = (float*)d_out;

    const size_t smem1 = (size_t)(2 * 4608 + 2 * 4224) * sizeof(float);              // 70656
    const size_t smem2 = (size_t)(2 * 2304 + 2 * 4224 + 1024 + 128) * sizeof(float); // 56832
    const size_t smem3 = (size_t)(2 * 2304 + 2 * 4224) * sizeof(float);              // 52224
    static bool attr_done = false;
    if (!attr_done) {
        cudaFuncSetAttribute(qkv_gemm_kernel,
                             cudaFuncAttributeMaxDynamicSharedMemorySize, (int)smem1);
        cudaFuncSetAttribute(score_diag_kernel,
                             cudaFuncAttributeMaxDynamicSharedMemorySize, (int)smem2);
        cudaFuncSetAttribute(out_gemm_kernel,
                             cudaFuncAttributeMaxDynamicSharedMemorySize, (int)smem3);
        attr_done = true;
    }

    qkv_gemm_kernel<<<dim3(kC3 / 128, kRows / 128), 256, smem1>>>(x, Wqkv, bqkv);
    transpose_qk_kernel<<<2048, 256>>>();
    score_diag_kernel<<<dim3(kN / 128, kB * kH, 16), 256, smem2>>>();
    finish_diag<<<128, 256>>>();
    av_kernel<<<8192, 256>>>();
    out_gemm_kernel<<<dim3(kD / 128, kRows / 64, 8), 256, smem3>>>(W0);
    out_combine<<<1024, 256>>>(b0, out);
}

// round 17
// speedup vs baseline: 1.1907x; 1.0235x over previous
#include <cuda_runtime.h>
#include <cstdint>

// Problem constants
constexpr int kB = 4;
constexpr int kN = 1024;
constexpr int kD = 256;
constexpr int kH = 8;
constexpr int kDH  = kD * kH;          // 2048
constexpr int kNDH = kN * kDH;         // 2097152
constexpr int kSeg = kB * kNDH;        // 8388608  (q/k/v segment, floats)
constexpr int kC3  = 3 * kDH;          // 6144
constexpr int kRows = kB * kN;         // 4096

// Scratch (device globals; no dynamic allocation allowed)
__device__ float g_qkv[3ull * kSeg];   // ~100.7 MB : QKV in reference flat layout
__device__ float g_qkT[2ull * kSeg];   // seg0: Q n-major scaled [bh][n][d]; reused as Av
                                       // seg1: K d-major       [bh][d][n]
__device__ float g_diag[kRows * kH];
__device__ float g_pcs[8 * 32 * kN];      // k2 partial colsums [z][bh][n]
__device__ float g_diagexp[32 * kN];      // exp(S[n,n]) per [bh][n]
__device__ float g_part8[8][kRows * kD];  // k3 K-split partials (32 MB)

// ---------------- cp.async helpers ----------------
__device__ __forceinline__ void cp16(void* smem_dst, const void* gmem_src) {
    unsigned s = (unsigned)__cvta_generic_to_shared(smem_dst);
    asm volatile("cp.async.cg.shared.global [%0], [%1], 16;\n" :: "r"(s), "l"(gmem_src));
}
__device__ __forceinline__ void cp_commit() {
    asm volatile("cp.async.commit_group;\n");
}
template <int N>
__device__ __forceinline__ void cp_wait() {
    asm volatile("cp.async.wait_group %0;\n" :: "n"(N));
}

// ---------------- packed f32x2 helpers (Blackwell FFMA2) ----------------
__device__ __forceinline__ void ffma2(uint64_t& d, uint64_t a, uint64_t b) {
    asm("fma.rn.f32x2 %0, %1, %2, %0;" : "+l"(d) : "l"(a), "l"(b));
}
__device__ __forceinline__ uint64_t bcast2(float x) {
    uint64_t r;
    asm("mov.b64 %0, {%1, %1};" : "=l"(r) : "r"(__float_as_uint(x)));
    return r;
}
__device__ __forceinline__ float2 unpk2(uint64_t v) {
    uint32_t lo, hi;
    asm("mov.b64 {%0, %1}, %2;" : "=r"(lo), "=r"(hi) : "l"(v));
    return make_float2(__uint_as_float(lo), __uint_as_float(hi));
}
__device__ __forceinline__ float selc(float4 v, int kk) {
    return (kk == 0) ? v.x : (kk == 1) ? v.y : (kk == 2) ? v.z : v.w;
}

// Shared inner-loop: one 32-k chunk of a 128x128 tile.
// A_ m-major [128][36]; B_ k-major [32][132].
__device__ __forceinline__ void mma_chunk(const float* __restrict__ A_,
                                          const float* __restrict__ B_,
                                          uint64_t (&acc)[8][4],
                                          int wm, int wn, int rowg, int colg)
{
#pragma unroll
    for (int kg = 0; kg < 32; kg += 4) {
        float4 av[8];
#pragma unroll
        for (int r = 0; r < 8; r++)
            av[r] = *(const float4*)&A_[(wm * 64 + r * 8 + rowg) * 36 + kg];
#pragma unroll
        for (int kk = 0; kk < 4; kk++) {
            const float* brow = &B_[(kg + kk) * 132 + wn * 32 + colg * 8];
            ulonglong2 q0 = *(const ulonglong2*)brow;
            ulonglong2 q1 = *(const ulonglong2*)(brow + 4);
#pragma unroll
            for (int r = 0; r < 8; r++) {
                uint64_t a2 = bcast2(selc(av[r], kk));
                ffma2(acc[r][0], a2, q0.x);
                ffma2(acc[r][1], a2, q0.y);
                ffma2(acc[r][2], a2, q1.x);
                ffma2(acc[r][3], a2, q1.y);
            }
        }
    }
}

// 64-row variant (CTA 64m x 128n, thread 4x8).
__device__ __forceinline__ void mma_chunk64(const float* __restrict__ A_,
                                            const float* __restrict__ B_,
                                            uint64_t (&acc)[4][4],
                                            int wm, int wn, int rowg, int colg)
{
#pragma unroll
    for (int kg = 0; kg < 32; kg += 4) {
        float4 av[4];
#pragma unroll
        for (int r = 0; r < 4; r++)
            av[r] = *(const float4*)&A_[(wm * 32 + r * 8 + rowg) * 36 + kg];
#pragma unroll
        for (int kk = 0; kk < 4; kk++) {
            const float* brow = &B_[(kg + kk) * 132 + wn * 32 + colg * 8];
            ulonglong2 q0 = *(const ulonglong2*)brow;
            ulonglong2 q1 = *(const ulonglong2*)(brow + 4);
#pragma unroll
            for (int r = 0; r < 4; r++) {
                uint64_t a2 = bcast2(selc(av[r], kk));
                ffma2(acc[r][0], a2, q0.x);
                ffma2(acc[r][1], a2, q0.y);
                ffma2(acc[r][2], a2, q1.x);
                ffma2(acc[r][3], a2, q1.y);
            }
        }
    }
}

// ---------------------------------------------------------------------------
// Kernel 1: QKV = x @ Wqkv + bqkv     [4096,256] @ [256,6144]
// CTA 128x128, warp 64x32, thread 8x8 packed, single-sync 2-stage pipeline.
// grid(48, 32) = 1536 CTAs. (round-14 proven, verbatim)
// ---------------------------------------------------------------------------
__global__ __launch_bounds__(256, 2)
void qkv_gemm_kernel(const float* __restrict__ x,
                     const float* __restrict__ W,
                     const float* __restrict__ bias)
{
    extern __shared__ float sm[];
    float* As = sm;                 // [2][128*36]
    float* Bs = sm + 2 * 4608;      // [2][32*132]

    const int t = threadIdx.x, lane = t & 31, w = t >> 5;
    const int wm = w & 1, wn = w >> 1;
    const int rowg = lane >> 2, colg = lane & 3;
    const int r0 = blockIdx.y * 128, c0 = blockIdx.x * 128;

    const int ar = t >> 3, ap = t & 7;
    const int bp = t & 31, br = t >> 5;

    uint64_t acc[8][4] = {};

    auto issue = [&](int buf, int kc) {
#pragma unroll
        for (int j = 0; j < 4; j++) {
            int m = ar + 32 * j;
            cp16(&As[buf * 4608 + m * 36 + ap * 4],
                 &x[(size_t)(r0 + m) * kD + kc + ap * 4]);
        }
#pragma unroll
        for (int i = 0; i < 4; i++) {
            int k = br + 8 * i;
            cp16(&Bs[buf * 4224 + k * 132 + bp * 4],
                 &W[(size_t)(kc + k) * kC3 + c0 + bp * 4]);
        }
        cp_commit();
    };

    issue(0, 0);
    for (int c = 0; c < 8; c++) {
        const int buf = c & 1;
        cp_wait<0>();
        __syncthreads();
        if (c < 7) issue(buf ^ 1, (c + 1) * 32);
        mma_chunk(&As[buf * 4608], &Bs[buf * 4224], acc, wm, wn, rowg, colg);
    }

    const int cbase = c0 + wn * 32 + colg * 8;
#pragma unroll
    for (int r = 0; r < 8; r++) {
        int row = r0 + wm * 64 + r * 8 + rowg;
        float2 u0 = unpk2(acc[r][0]), u1 = unpk2(acc[r][1]);
        float2 u2 = unpk2(acc[r][2]), u3 = unpk2(acc[r][3]);
        float4 v0, v1;
        v0.x = u0.x + bias[cbase + 0]; v0.y = u0.y + bias[cbase + 1];
        v0.z = u1.x + bias[cbase + 2]; v0.w = u1.y + bias[cbase + 3];
        v1.x = u2.x + bias[cbase + 4]; v1.y = u2.y + bias[cbase + 5];
        v1.z = u3.x + bias[cbase + 6]; v1.w = u3.y + bias[cbase + 7];
        *(float4*)&g_qkv[(size_t)row * kC3 + cbase] = v0;
        *(float4*)&g_qkv[(size_t)row * kC3 + cbase + 4] = v1;
    }
}

// ---------------------------------------------------------------------------
// Transpose: q -> [bh][n][d] (scaled 1/16);  k -> [bh][d][n]. (proven, verbatim)
// ---------------------------------------------------------------------------
__global__ __launch_bounds__(256)
void transpose_qk_kernel()
{
    __shared__ float smt[8][32][33];   // [h][qd][n]
    const int bid = blockIdx.x;
    const int qb  = bid & 7;
    const int nb  = (bid >> 3) & 31;
    const int b   = (bid >> 8) & 3;
    const int seg = bid >> 10;
    const int t   = threadIdx.x;

    const float* src = g_qkv + (size_t)seg * kSeg + (size_t)b * kNDH
                     + (size_t)(nb * 32) * kDH + qb * 32 * 8;
    {
        const int nl = t >> 3, f = t & 7;
        const int h0 = (f & 1) * 4, q0 = f >> 1;
#pragma unroll
        for (int i = 0; i < 8; i++) {
            float4 v = *(const float4*)&src[(size_t)nl * kDH + (f + i * 8) * 4];
            int ql = q0 + i * 4;
            smt[h0 + 0][ql][nl] = v.x;
            smt[h0 + 1][ql][nl] = v.y;
            smt[h0 + 2][ql][nl] = v.z;
            smt[h0 + 3][ql][nl] = v.w;
        }
    }
    __syncthreads();
    if (seg == 0) {
        const int q4 = (t & 7) * 4, hn = t >> 3;
#pragma unroll
        for (int i = 0; i < 8; i++) {
            int idx = hn + i * 32;
            int h = idx >> 5, n = idx & 31;
            float4 v;
            v.x = smt[h][q4 + 0][n] * 0.0625f;
            v.y = smt[h][q4 + 1][n] * 0.0625f;
            v.z = smt[h][q4 + 2][n] * 0.0625f;
            v.w = smt[h][q4 + 3][n] * 0.0625f;
            float* dst = g_qkT
                       + (((size_t)(b * 8 + h) * kN + nb * 32 + n) * kD)
                       + qb * 32 + q4;
            *(float4*)dst = v;
        }
    } else {
#pragma unroll
        for (int i = 0; i < 8; i++) {
            int idx = t + i * 256;
            int h = idx >> 8, rem = idx & 255;
            int q = rem >> 3, nf = rem & 7;
            float4 v;
            v.x = smt[h][q][nf * 4 + 0];
            v.y = smt[h][q][nf * 4 + 1];
            v.z = smt[h][q][nf * 4 + 2];
            v.w = smt[h][q][nf * 4 + 3];
            float* dst = g_qkT + (size_t)kSeg
                       + (((size_t)(b * 8 + h) * kD + qb * 32 + q) * kN)
                       + nb * 32 + nf * 4;
            *(float4*)dst = v;
        }
    }
}

// ---------------------------------------------------------------------------
// Kernel 2: per (b,h,z): colsums of exp(S) for ONE 128-m tile (m0 = z*128),
// plus diag-exp when z == n-tile. 3-stage cp.async pipeline (depth-2 prefetch).
// red/diagsm aliased onto As[0] (dead in final chunk: buf7 = 7%3 = 1).
// grid(8, 32, 8) = 2048 CTAs.
// ---------------------------------------------------------------------------
__global__ __launch_bounds__(256, 2)
void score_diag_kernel()
{
    extern __shared__ float sm[];
    float* As     = sm;                  // [3][128*36] = 3*4608
    float* Ks     = sm + 3 * 4608;       // [3][32*132] = 3*4224
    float* red    = sm;                  // [16*128] aliases As[0][0..2047]
    float* diagsm = sm + 2048;           // [128]    aliases As[0][2048..2175]

    const int t = threadIdx.x, lane = t & 31, w = t >> 5;
    const int wm = w & 1, wn = w >> 1;
    const int rowg = lane >> 2, colg = lane & 3;
    const int bh = blockIdx.y;
    const int n0 = blockIdx.x * 128;
    const int z  = blockIdx.z;                 // m-tile 0..7
    const int m0 = z * 128;

    const float* Q  = g_qkT + (size_t)bh * (kN * kD);                 // [n][d]
    const float* Kd = g_qkT + (size_t)kSeg + (size_t)bh * (kD * kN);  // [d][n]

    const int ar = t >> 3, ap = t & 7;
    const int bp = t & 31, br = t >> 5;

    const bool diagtile = (z == (int)blockIdx.x);

    uint64_t acc[8][4] = {};

    auto issue = [&](int buf, int kc) {
#pragma unroll
        for (int j = 0; j < 4; j++) {
            int m = ar + 32 * j;
            cp16(&As[buf * 4608 + m * 36 + ap * 4],
                 &Q[(size_t)(m0 + m) * kD + kc + ap * 4]);
        }
#pragma unroll
        for (int i = 0; i < 4; i++) {
            int k = br + 8 * i;
            cp16(&Ks[buf * 4224 + k * 132 + bp * 4],
                 &Kd[(size_t)(kc + k) * kN + n0 + bp * 4]);
        }
        cp_commit();
    };

    issue(0, 0);
    issue(1, 32);
    for (int c = 0; c < 8; c++) {
        const int buf = c % 3;
        if (c < 7) cp_wait<1>(); else cp_wait<0>();
        __syncthreads();
        if (c < 6) issue((c + 2) % 3, (c + 2) * 32);
        mma_chunk(&As[buf * 4608], &Ks[buf * 4224], acc, wm, wn, rowg, colg);
    }

    // ---- epilogue: exp + colsum; diagonal -> smem ----
    // red/diagsm alias As[0]; final two mma chunks used bufs 0(c=6),1(c=7):
    // mma(6) on As[0] completed before the c=7 __syncthreads, so each thread
    // writing red now only races threads still in mma(7) on As[1]/Ks[1]. Safe.
    float colsum[8];
    const int clb = wn * 32 + colg * 8;
#pragma unroll
    for (int jp = 0; jp < 4; jp++) {
        float s0 = 0.f, s1 = 0.f;
#pragma unroll
        for (int r = 0; r < 8; r++) {
            float2 u = unpk2(acc[r][jp]);
            float e0 = __expf(u.x), e1 = __expf(u.y);
            s0 += e0; s1 += e1;
            if (diagtile) {
                int lm = wm * 64 + r * 8 + rowg;
                if (lm == clb + 2 * jp)     diagsm[clb + 2 * jp]     = e0;
                if (lm == clb + 2 * jp + 1) diagsm[clb + 2 * jp + 1] = e1;
            }
        }
        colsum[2 * jp]     = s0;
        colsum[2 * jp + 1] = s1;
    }

    // Wait: mma(6) read As[0] and finished before the last sync, but mma(7)
    // readers don't touch As[0]; still need all threads past their own use of
    // the aliased region before reads below -> the existing barrier suffices.
    const int slot = wm * 8 + rowg;
#pragma unroll
    for (int j = 0; j < 8; j++)
        red[slot * 128 + clb + j] = colsum[j];
    __syncthreads();
    if (t < 128) {
        float total = red[t];
#pragma unroll
        for (int r = 1; r < 16; r++) total += red[r * 128 + t];
        g_pcs[((size_t)z * 32 + bh) * kN + n0 + t] = total;
        if (diagtile)
            g_diagexp[(size_t)bh * kN + n0 + t] = diagsm[t];
    }
}

// ---------------------------------------------------------------------------
// Kernel 2b: g_diag = diagexp / sum_z pcs  (8 slices)
// ---------------------------------------------------------------------------
__global__ __launch_bounds__(256)
void finish_diag()
{
    int id = blockIdx.x * 256 + threadIdx.x;   // 32768 = 32 bh x 1024 n
    int bh = id >> 10, n = id & 1023;
    float tot = 0.f;
#pragma unroll
    for (int z = 0; z < 8; z++)
        tot += g_pcs[((size_t)z * 32 + bh) * kN + n];
    int b = bh >> 3, h = bh & 7;
    g_diag[((size_t)b * kN + n) * kH + h] = g_diagexp[(size_t)bh * kN + n] / tot;
}

// ---------------------------------------------------------------------------
// Kernel 2c: Av = diag .* v  -> g_qkT seg0 (Q dead after k2). (proven)
// ---------------------------------------------------------------------------
__global__ __launch_bounds__(256)
void av_kernel()
{
    const float* vseg = g_qkv + 2ull * kSeg;
    int idx = (blockIdx.x * 256 + threadIdx.x) * 4;
    int r = idx >> 11;
    int c = idx & 2047;
    float4 v = *(const float4*)&vseg[idx];
    float4 dv = *(const float4*)&g_diag[r * 8 + (c & 4)];
    v.x *= dv.x; v.y *= dv.y; v.z *= dv.z; v.w *= dv.w;
    *(float4*)&g_qkT[idx] = v;
}

// ---------------------------------------------------------------------------
// Kernel 3: partial = Av @ W0, K-split 8.  [4096,2048]@[2048,256]
// CTA 64m x 128n, thread 4x8 packed, 3-stage cp.async pipeline.
// grid(2, 64, 8) = 1024 CTAs.
// ---------------------------------------------------------------------------
__global__ __launch_bounds__(256, 2)
void out_gemm_kernel(const float* __restrict__ W0)
{
    extern __shared__ float sm[];
    float* As = sm;                 // [3][64*36]  = 3*2304
    float* Ws = sm + 3 * 2304;      // [3][32*132] = 3*4224

    const int t = threadIdx.x, lane = t & 31, w = t >> 5;
    const int wm = w & 1, wn = w >> 1;
    const int rowg = lane >> 2, colg = lane & 3;
    const int c0 = blockIdx.x * 128;
    const int r0 = blockIdx.y * 64;
    const int kb = blockIdx.z * 256;
    float* dst = g_part8[blockIdx.z];

    const int ar = t >> 3, ap = t & 7;
    const int bp = t & 31, br = t >> 5;

    uint64_t acc[4][4] = {};

    auto issue = [&](int buf, int kc) {
#pragma unroll
        for (int j = 0; j < 2; j++) {
            int m = ar + 32 * j;
            cp16(&As[buf * 2304 + m * 36 + ap * 4],
                 &g_qkT[(size_t)(r0 + m) * kDH + kb + kc + ap * 4]);
        }
#pragma unroll
        for (int i = 0; i < 4; i++) {
            int k = br + 8 * i;
            cp16(&Ws[buf * 4224 + k * 132 + bp * 4],
                 &W0[(size_t)(kb + kc + k) * kD + c0 + bp * 4]);
        }
        cp_commit();
    };

    issue(0, 0);
    issue(1, 32);
    for (int c = 0; c < 8; c++) {
        const int buf = c % 3;
        if (c < 7) cp_wait<1>(); else cp_wait<0>();
        __syncthreads();
        if (c < 6) issue((c + 2) % 3, (c + 2) * 32);
        mma_chunk64(&As[buf * 2304], &Ws[buf * 4224], acc, wm, wn, rowg, colg);
    }

    const int cbase = c0 + wn * 32 + colg * 8;
#pragma unroll
    for (int r = 0; r < 4; r++) {
        int row = r0 + wm * 32 + r * 8 + rowg;
        float2 u0 = unpk2(acc[r][0]), u1 = unpk2(acc[r][1]);
        float2 u2 = unpk2(acc[r][2]), u3 = unpk2(acc[r][3]);
        float4 v0 = {u0.x, u0.y, u1.x, u1.y};
        float4 v1 = {u2.x, u2.y, u3.x, u3.y};
        *(float4*)&dst[(size_t)row * kD + cbase] = v0;
        *(float4*)&dst[(size_t)row * kD + cbase + 4] = v1;
    }
}

// ---------------------------------------------------------------------------
// Kernel 3b: out = sum of 8 partials + b0
// ---------------------------------------------------------------------------
__global__ __launch_bounds__(256)
void out_combine(const float* __restrict__ b0, float* __restrict__ out)
{
    int i4 = blockIdx.x * 256 + threadIdx.x;     // float4 index, 262144 total
    size_t off = (size_t)i4 * 4;
    float4 s = *(const float4*)&g_part8[0][off];
#pragma unroll
    for (int z = 1; z < 8; z++) {
        float4 p = *(const float4*)&g_part8[z][off];
        s.x += p.x; s.y += p.y; s.z += p.z; s.w += p.w;
    }
    float4 bb = *(const float4*)&b0[(i4 & 63) * 4];
    s.x += bb.x; s.y += bb.y; s.z += bb.z; s.w += bb.w;
    *(float4*)&out[off] = s;
}

// ---------------------------------------------------------------------------
extern "C" void kernel_launch(void* const* d_in, const int* in_sizes, int n_in,
                              void* d_out, int out_size)
{
    const float *x = nullptr, *Wqkv = nullptr, *bqkv = nullptr,
                *W0 = nullptr, *b0 = nullptr;
    for (int i = 0; i < n_in; i++) {
        switch (in_sizes[i]) {
            case kRows * kD: x    = (const float*)d_in[i]; break;
            case kD * kC3:   Wqkv = (const float*)d_in[i]; break;
            case kC3:        bqkv = (const float*)d_in[i]; break;
            case kDH * kD:   W0   = (const float*)d_in[i]; break;
            case kD:         b0   = (const float*)d_in[i]; break;
            default: break;
        }
    }
    float* out = (float*)d_out;

    const size_t smem1 = (size_t)(2 * 4608 + 2 * 4224) * sizeof(float);   // 70656
    const size_t smem2 = (size_t)(3 * 4608 + 3 * 4224) * sizeof(float);   // 105984
    const size_t smem3 = (size_t)(3 * 2304 + 3 * 4224) * sizeof(float);   // 78336
    static bool attr_done = false;
    if (!attr_done) {
        cudaFuncSetAttribute(qkv_gemm_kernel,
                             cudaFuncAttributeMaxDynamicSharedMemorySize, (int)smem1);
        cudaFuncSetAttribute(score_diag_kernel,
                             cudaFuncAttributeMaxDynamicSharedMemorySize, (int)smem2);
        cudaFuncSetAttribute(out_gemm_kernel,
                             cudaFuncAttributeMaxDynamicSharedMemorySize, (int)smem3);
        attr_done = true;
    }

    qkv_gemm_kernel<<<dim3(kC3 / 128, kRows / 128), 256, smem1>>>(x, Wqkv, bqkv);
    transpose_qk_kernel<<<2048, 256>>>();
    score_diag_kernel<<<dim3(kN / 128, kB * kH, 8), 256, smem2>>>();
    finish_diag<<<128, 256>>>();
    av_kernel<<<8192, 256>>>();
    out_gemm_kernel<<<dim3(kD / 128, kRows / 64, 8), 256, smem3>>>(W0);
    out_combine<<<1024, 256>>>(b0, out);
}